// round 12
// baseline (speedup 1.0000x reference)
#include <cuda_runtime.h>
#include <cstdint>

#define CIN   32
#define COUTD 32
#define HDIM  128
#define WDIM  128
#define BDIM  4
#define PLANE (HDIM * WDIM)
#define OUTPLANE (BDIM * COUTD * PLANE)   /* 2097152 */
#define CSLICE (9 * COUTD * 12)           /* floats per channel slice: 3456 */

typedef unsigned long long u64;

// Coefficient table: per (cin, tap, cout): 12 floats (duplicated pairs):
// {c0,c0, s0,s0, wa,wa, wb,wb, wc,wc, wd,wd}  -> 48B per entry
__device__ __align__(16) float g_coef[CIN * CSLICE];

// ---------------- packed f32x2 helpers ----------------
static __device__ __forceinline__ u64 mul2(u64 a, u64 b) {
    u64 d; asm("mul.rn.f32x2 %0, %1, %2;" : "=l"(d) : "l"(a), "l"(b)); return d;
}
static __device__ __forceinline__ u64 fma2(u64 a, u64 b, u64 c) {
    u64 d; asm("fma.rn.f32x2 %0, %1, %2, %3;" : "=l"(d) : "l"(a), "l"(b), "l"(c)); return d;
}
static __device__ __forceinline__ u64 sub2(u64 a, u64 b) {
    u64 d; asm("sub.rn.f32x2 %0, %1, %2;" : "=l"(d) : "l"(a), "l"(b)); return d;
}
static __device__ __forceinline__ void unpack2(u64 a, float& lo, float& hi) {
    asm("mov.b64 {%0, %1}, %2;" : "=f"(lo), "=f"(hi) : "l"(a));
}
static __device__ __forceinline__ u64 pack2(float lo, float hi) {
    u64 d; asm("mov.b64 %0, {%1, %2};" : "=l"(d) : "f"(lo), "f"(hi)); return d;
}
static __device__ __forceinline__ u64 relu2(u64 a) {
    float lo, hi; unpack2(a, lo, hi);
    return pack2(fmaxf(lo, 0.f), fmaxf(hi, 0.f));
}

// ---------------- coefficient precompute ----------------
// e = (c*9 + tap)*32 + o
__global__ void precompute_kernel(const float* __restrict__ w,
                                  const float* __restrict__ wr) {
    int e = blockIdx.x * blockDim.x + threadIdx.x;
    if (e >= CIN * 9 * COUTD) return;
    int o   = e & 31;
    int tap = (e >> 5) % 9;
    int c   = e / (9 * COUTD);
    int i = tap / 3, j = tap % 3;

    const float* wrb = wr + (size_t)(o * CIN + c) * 9;
    const float* wb_ = w  + (size_t)(o * CIN + c) * 9;

    float ang = wrb[i * 3 + j];
    float s0, c0;
    sincosf(ang, &s0, &c0);

    // orientation-k weight = w rotated k times; rot1: wk[i,j] = w[2-j, i]
    float wa = wb_[i * 3 + j];                 // k=0, pairs with relu(u)
    float wb = wb_[(2 - j) * 3 + i];           // k=1, pairs with relu(v)
    float wc = wb_[(2 - i) * 3 + (2 - j)];     // k=2, pairs with relu(-u)
    float wd = wb_[j * 3 + (2 - i)];           // k=3, pairs with relu(-v)

    float* dst = g_coef + (size_t)e * 12;
    dst[0] = c0; dst[1] = c0;
    dst[2] = s0; dst[3] = s0;
    dst[4] = wa; dst[5] = wa;
    dst[6] = wb; dst[7] = wb;
    dst[8] = wc; dst[9] = wc;
    dst[10] = wd; dst[11] = wd;
}

// ---------------- main kernel ----------------
// Block: one (b, h, cout-half). 128 threads = 4 warps; warp w handles couts
// [blockIdx.y*16 + w*4, +4). Each lane handles P=2 packed pixel-pairs:
//   pair0 = (lane,     lane+64),  pair1 = (lane+32, lane+96)
// Warp-level economy identical to the 415us kernel; only block granularity is
// halved (1024 blocks) to shrink the last-wave tail.
__global__ void __launch_bounds__(128, 4)
orient_conv_kernel(const float* __restrict__ f,
                   const float* __restrict__ r0,
                   const float* __restrict__ r1,
                   float* __restrict__ out) {
    __shared__ float2 sm[2][3][3][66];   // [buf][array][row][entry]

    const int tid   = threadIdx.x;
    const int lane  = tid & 31;
    const int warp  = tid >> 5;
    const int cout0 = blockIdx.y * 16 + warp * 4;
    const int h     = blockIdx.x;
    const int b     = blockIdx.z;

    const u64 SGN = 0x8000000080000000ull;

    u64 acc[4][4][2];                    // [oc][orient][pair]
#pragma unroll
    for (int oc = 0; oc < 4; ++oc)
#pragma unroll
        for (int t = 0; t < 4; ++t) { acc[oc][t][0] = 0ull; acc[oc][t][1] = 0ull; }

    auto prefetch = [&](int c, int buf) {
        const size_t chanoff = (size_t)(b * CIN + c) * PLANE;
        const float* pf = f  + chanoff;
        const float* p0 = r0 + chanoff;
        const float* p1 = r1 + chanoff;
        for (int idx = tid; idx < 594; idx += 128) {   // 3 arrays * 3 rows * 66 entries
            int a   = idx / 198;
            int rem = idx - a * 198;
            int r   = rem / 66;
            int kk  = rem - r * 66;
            int row = h - 1 + r;
            const float* p = (a == 0) ? pf : (a == 1) ? p0 : p1;
            float x1 = 0.f, x2 = 0.f;
            if ((unsigned)row < (unsigned)HDIM) {
                const float* pr = p + (size_t)row * WDIM;
                int g = kk - 1;                       // -1..64
                if (g >= 0) x1 = pr[g];
                if (g + 64 < WDIM) x2 = pr[g + 64];
            }
            sm[buf][a][r][kk] = make_float2(x1, x2);
        }
    };

    prefetch(0, 0);
    __syncthreads();

#pragma unroll 1
    for (int c = 0; c < CIN; ++c) {
        if (c + 1 < CIN) prefetch(c + 1, (c + 1) & 1);
        const int buf = c & 1;
        const ulonglong2* __restrict__ ctc =
            reinterpret_cast<const ulonglong2*>(g_coef) +
            ((size_t)(c * 9) * COUTD + cout0) * 3;

        // operand double buffers: [sel][pair]
        u64 Fb[2][2], R0b[2][2], R1b[2][2];

        auto load_ops = [&](int tap, int sel) {
            const int i = tap / 3, j = tap % 3;
#pragma unroll
            for (int p = 0; p < 2; ++p) {
                const int ent = lane + p * 32 + j;
                Fb[sel][p]  = *reinterpret_cast<const u64*>(&sm[buf][0][i][ent]);
                R0b[sel][p] = *reinterpret_cast<const u64*>(&sm[buf][1][i][ent]);
                R1b[sel][p] = *reinterpret_cast<const u64*>(&sm[buf][2][i][ent]);
            }
        };

        load_ops(0, 0);
        ulonglong2 L0 = __ldg(ctc + 0);
        ulonglong2 L1 = __ldg(ctc + 1);
        ulonglong2 L2 = __ldg(ctc + 2);
        int ob = 0;

#pragma unroll
        for (int t = 0; t < 36; ++t) {
            const int tap = t >> 2;
            const int oc  = t & 3;

            // 1) issue next step's coefficient loads
            ulonglong2 N0, N1, N2;
            if (t < 35) {
                const ulonglong2* np = ctc + (size_t)((t + 1) >> 2) * (COUTD * 3)
                                           + (size_t)((t + 1) & 3) * 3;
                N0 = __ldg(np + 0); N1 = __ldg(np + 1); N2 = __ldg(np + 2);
            }
            // 2) issue next tap's operand loads during this tap's last oc
            if (oc == 3 && tap < 8) load_ops(tap + 1, ob ^ 1);

            const u64 NS = L0.y ^ SGN;   // packed -s

            // 3) math for (tap, oc) on both pairs
#pragma unroll
            for (int p = 0; p < 2; ++p) {
                u64 u = fma2(L0.x, R0b[ob][p], mul2(L0.y, R1b[ob][p])); // c*r0+s*r1
                u64 v = fma2(NS,   R0b[ob][p], mul2(L0.x, R1b[ob][p])); // c*r1-s*r0

                u64 PU  = relu2(u);
                u64 PV  = relu2(v);
                u64 Fu  = mul2(Fb[ob][p], u);
                u64 Fv  = mul2(Fb[ob][p], v);
                u64 FPU = mul2(Fb[ob][p], PU);
                u64 FPV = mul2(Fb[ob][p], PV);
                u64 FMU = sub2(FPU, Fu);   // F*relu(-u) = F*relu(u) - F*u
                u64 FMV = sub2(FPV, Fv);   // F*relu(-v) = F*relu(v) - F*v

                acc[oc][0][p] = fma2(L1.x, FPU, acc[oc][0][p]);
                acc[oc][1][p] = fma2(L1.y, FPV, acc[oc][1][p]);
                acc[oc][2][p] = fma2(L2.x, FMU, acc[oc][2][p]);
                acc[oc][3][p] = fma2(L2.y, FMV, acc[oc][3][p]);
            }

            if (oc == 3) ob ^= 1;
            if (t < 35) { L0 = N0; L1 = N1; L2 = N2; }
        }
        __syncthreads();
    }

    // Epilogue: first-max argmax over the 4 orientations; write out / cos / sin.
#pragma unroll
    for (int oc = 0; oc < 4; ++oc) {
#pragma unroll
        for (int p = 0; p < 2; ++p) {
            float v0l, v0h, v1l, v1h, v2l, v2h, v3l, v3h;
            unpack2(acc[oc][0][p], v0l, v0h);
            unpack2(acc[oc][1][p], v1l, v1h);
            unpack2(acc[oc][2][p], v2l, v2h);
            unpack2(acc[oc][3][p], v3l, v3h);

            const int col = lane + p * 32;
            size_t base = ((size_t)(b * COUTD + cout0 + oc) * HDIM + h) * WDIM + col;

            {   // lo half: w = col
                float best = v0l; int idx = 0;
                if (v1l > best) { best = v1l; idx = 1; }
                if (v2l > best) { best = v2l; idx = 2; }
                if (v3l > best) { best = v3l; idx = 3; }
                float cv = (idx == 0) ? 1.0f : (idx == 1) ? -4.371139e-8f
                           : (idx == 2) ? -1.0f : 1.1924881e-8f;
                float sv = (idx == 0) ? 0.0f : (idx == 1) ? 1.0f
                           : (idx == 2) ? -8.742278e-8f : -1.0f;
                out[base]                = best;
                out[base + OUTPLANE]     = cv;
                out[base + 2 * OUTPLANE] = sv;
            }
            {   // hi half: w = col + 64
                float best = v0h; int idx = 0;
                if (v1h > best) { best = v1h; idx = 1; }
                if (v2h > best) { best = v2h; idx = 2; }
                if (v3h > best) { best = v3h; idx = 3; }
                float cv = (idx == 0) ? 1.0f : (idx == 1) ? -4.371139e-8f
                           : (idx == 2) ? -1.0f : 1.1924881e-8f;
                float sv = (idx == 0) ? 0.0f : (idx == 1) ? 1.0f
                           : (idx == 2) ? -8.742278e-8f : -1.0f;
                out[base + 64]                = best;
                out[base + 64 + OUTPLANE]     = cv;
                out[base + 64 + 2 * OUTPLANE] = sv;
            }
        }
    }
}

extern "C" void kernel_launch(void* const* d_in, const int* in_sizes, int n_in,
                              void* d_out, int out_size) {
    const float* f  = (const float*)d_in[0];
    const float* r0 = (const float*)d_in[1];
    const float* r1 = (const float*)d_in[2];
    const float* w  = (const float*)d_in[3];
    const float* wr = (const float*)d_in[4];

    precompute_kernel<<<(CIN * 9 * COUTD + 255) / 256, 256>>>(w, wr);

    dim3 grid(HDIM, 2, BDIM);
    orient_conv_kernel<<<grid, 128>>>(f, r0, r1, (float*)d_out);
}

// round 13
// speedup vs baseline: 1.3995x; 1.3995x over previous
#include <cuda_runtime.h>
#include <cstdint>

#define CIN   32
#define COUTD 32
#define HDIM  128
#define WDIM  128
#define BDIM  4
#define PLANE (HDIM * WDIM)
#define OUTPLANE (BDIM * COUTD * PLANE)   /* 2097152 */
#define CSLICE (9 * COUTD * 12)           /* floats per channel slice: 3456 */

typedef unsigned long long u64;

// Coefficient table: per (cin, tap, cout): 12 floats (duplicated pairs):
// {c0,c0, s0,s0, wa,wa, wb,wb, -wc,-wc, -wd,-wd}  -> 48B per entry
// (wc, wd stored NEGATED: the relu(-x) sign is folded into the weight)
__device__ __align__(16) float g_coef[CIN * CSLICE];

// ---------------- packed f32x2 helpers ----------------
static __device__ __forceinline__ u64 mul2(u64 a, u64 b) {
    u64 d; asm("mul.rn.f32x2 %0, %1, %2;" : "=l"(d) : "l"(a), "l"(b)); return d;
}
static __device__ __forceinline__ u64 fma2(u64 a, u64 b, u64 c) {
    u64 d; asm("fma.rn.f32x2 %0, %1, %2, %3;" : "=l"(d) : "l"(a), "l"(b), "l"(c)); return d;
}
static __device__ __forceinline__ void unpack2(u64 a, float& lo, float& hi) {
    asm("mov.b64 {%0, %1}, %2;" : "=f"(lo), "=f"(hi) : "l"(a));
}
// per-half sign mask: 0xFFFFFFFF where that half is negative, else 0
static __device__ __forceinline__ u64 signmask2(u64 x) {
    uint32_t lo = (uint32_t)x;
    uint32_t hi = (uint32_t)(x >> 32);
    uint32_t ml = (uint32_t)(((int32_t)lo) >> 31);
    uint32_t mh = (uint32_t)(((int32_t)hi) >> 31);
    return ((u64)mh << 32) | (u64)ml;
}

// ---------------- coefficient precompute ----------------
// e = (c*9 + tap)*32 + o
__global__ void precompute_kernel(const float* __restrict__ w,
                                  const float* __restrict__ wr) {
    int e = blockIdx.x * blockDim.x + threadIdx.x;
    if (e >= CIN * 9 * COUTD) return;
    int o   = e & 31;
    int tap = (e >> 5) % 9;
    int c   = e / (9 * COUTD);
    int i = tap / 3, j = tap % 3;

    const float* wrb = wr + (size_t)(o * CIN + c) * 9;
    const float* wb_ = w  + (size_t)(o * CIN + c) * 9;

    float ang = wrb[i * 3 + j];
    float s0, c0;
    sincosf(ang, &s0, &c0);

    // orientation-k weight = w rotated k times; rot1: wk[i,j] = w[2-j, i]
    float wa = wb_[i * 3 + j];                 // k=0, pairs with relu(u)
    float wb = wb_[(2 - j) * 3 + i];           // k=1, pairs with relu(v)
    float wc = wb_[(2 - i) * 3 + (2 - j)];     // k=2, pairs with relu(-u)
    float wd = wb_[j * 3 + (2 - i)];           // k=3, pairs with relu(-v)

    float* dst = g_coef + (size_t)e * 12;
    dst[0] = c0;  dst[1] = c0;
    dst[2] = s0;  dst[3] = s0;
    dst[4] = wa;  dst[5] = wa;
    dst[6] = wb;  dst[7] = wb;
    dst[8]  = -wc; dst[9]  = -wc;   // negated: acc2 += (-wc) * (Fu masked to u<0)
    dst[10] = -wd; dst[11] = -wd;   // negated: acc3 += (-wd) * (Fv masked to v<0)
}

// ---------------- main kernel ----------------
// Block: one (b, h) full row. 256 threads = 8 warps; warp w handles couts
// [w*4, w*4+4). Each lane handles P=2 packed pixel-pairs:
//   pair0 = (lane,     lane+64),  pair1 = (lane+32, lane+96)
// 36-step (tap,oc) software pipeline. Relu is done by sign-masking Fu/Fv on
// the ALU pipe (SHF+LOP3), cutting fp32-pipe ops from 14 to 10 per unit:
//   F*relu(u)  = Fu & ~sign(u),   wc*F*relu(-u) = (-wc) * (Fu & sign(u))
__global__ void __launch_bounds__(256, 2)
orient_conv_kernel(const float* __restrict__ f,
                   const float* __restrict__ r0,
                   const float* __restrict__ r1,
                   float* __restrict__ out) {
    __shared__ float2 sm[2][3][3][66];   // [buf][array][row][entry]

    const int tid   = threadIdx.x;
    const int lane  = tid & 31;
    const int warp  = tid >> 5;
    const int cout0 = warp * 4;
    const int h     = blockIdx.x;
    const int b     = blockIdx.y;

    const u64 SGN = 0x8000000080000000ull;

    u64 acc[4][4][2];                    // [oc][orient][pair]
#pragma unroll
    for (int oc = 0; oc < 4; ++oc)
#pragma unroll
        for (int t = 0; t < 4; ++t) { acc[oc][t][0] = 0ull; acc[oc][t][1] = 0ull; }

    auto prefetch = [&](int c, int buf) {
        const size_t chanoff = (size_t)(b * CIN + c) * PLANE;
        const float* pf = f  + chanoff;
        const float* p0 = r0 + chanoff;
        const float* p1 = r1 + chanoff;
        for (int idx = tid; idx < 594; idx += 256) {   // 3 arrays * 3 rows * 66 entries
            int a   = idx / 198;
            int rem = idx - a * 198;
            int r   = rem / 66;
            int kk  = rem - r * 66;
            int row = h - 1 + r;
            const float* p = (a == 0) ? pf : (a == 1) ? p0 : p1;
            float x1 = 0.f, x2 = 0.f;
            if ((unsigned)row < (unsigned)HDIM) {
                const float* pr = p + (size_t)row * WDIM;
                int g = kk - 1;                       // -1..64
                if (g >= 0) x1 = pr[g];
                if (g + 64 < WDIM) x2 = pr[g + 64];
            }
            sm[buf][a][r][kk] = make_float2(x1, x2);
        }
    };

    prefetch(0, 0);
    __syncthreads();

#pragma unroll 1
    for (int c = 0; c < CIN; ++c) {
        if (c + 1 < CIN) prefetch(c + 1, (c + 1) & 1);
        const int buf = c & 1;
        const ulonglong2* __restrict__ ctc =
            reinterpret_cast<const ulonglong2*>(g_coef) +
            ((size_t)(c * 9) * COUTD + cout0) * 3;

        // operand double buffers: [sel][pair]
        u64 Fb[2][2], R0b[2][2], R1b[2][2];

        auto load_ops = [&](int tap, int sel) {
            const int i = tap / 3, j = tap % 3;
#pragma unroll
            for (int p = 0; p < 2; ++p) {
                const int ent = lane + p * 32 + j;
                Fb[sel][p]  = *reinterpret_cast<const u64*>(&sm[buf][0][i][ent]);
                R0b[sel][p] = *reinterpret_cast<const u64*>(&sm[buf][1][i][ent]);
                R1b[sel][p] = *reinterpret_cast<const u64*>(&sm[buf][2][i][ent]);
            }
        };

        load_ops(0, 0);
        ulonglong2 L0 = __ldg(ctc + 0);
        ulonglong2 L1 = __ldg(ctc + 1);
        ulonglong2 L2 = __ldg(ctc + 2);
        int ob = 0;

#pragma unroll
        for (int t = 0; t < 36; ++t) {
            const int tap = t >> 2;
            const int oc  = t & 3;

            // 1) issue next step's coefficient loads
            ulonglong2 N0, N1, N2;
            if (t < 35) {
                const ulonglong2* np = ctc + (size_t)((t + 1) >> 2) * (COUTD * 3)
                                           + (size_t)((t + 1) & 3) * 3;
                N0 = __ldg(np + 0); N1 = __ldg(np + 1); N2 = __ldg(np + 2);
            }
            // 2) issue next tap's operand loads during this tap's last oc
            if (oc == 3 && tap < 8) load_ops(tap + 1, ob ^ 1);

            const u64 NS = L0.y ^ SGN;   // packed -s

            // 3) math for (tap, oc) on both pairs: 10 FFMA2 + masks on ALU
#pragma unroll
            for (int p = 0; p < 2; ++p) {
                u64 u = fma2(L0.x, R0b[ob][p], mul2(L0.y, R1b[ob][p])); // c*r0+s*r1
                u64 v = fma2(NS,   R0b[ob][p], mul2(L0.x, R1b[ob][p])); // c*r1-s*r0

                u64 Fu = mul2(Fb[ob][p], u);
                u64 Fv = mul2(Fb[ob][p], v);

                u64 mu = signmask2(u);      // all-ones halves where u<0
                u64 mv = signmask2(v);

                u64 FPU = Fu & ~mu;         // F*relu(u)
                u64 FMU = Fu & mu;          // F*u where u<0 (weight is -wc)
                u64 FPV = Fv & ~mv;
                u64 FMV = Fv & mv;

                acc[oc][0][p] = fma2(L1.x, FPU, acc[oc][0][p]);
                acc[oc][1][p] = fma2(L1.y, FPV, acc[oc][1][p]);
                acc[oc][2][p] = fma2(L2.x, FMU, acc[oc][2][p]);  // -wc * Fu[u<0]
                acc[oc][3][p] = fma2(L2.y, FMV, acc[oc][3][p]);  // -wd * Fv[v<0]
            }

            if (oc == 3) ob ^= 1;
            if (t < 35) { L0 = N0; L1 = N1; L2 = N2; }
        }
        __syncthreads();
    }

    // Epilogue: first-max argmax over the 4 orientations; write out / cos / sin.
#pragma unroll
    for (int oc = 0; oc < 4; ++oc) {
#pragma unroll
        for (int p = 0; p < 2; ++p) {
            float v0l, v0h, v1l, v1h, v2l, v2h, v3l, v3h;
            unpack2(acc[oc][0][p], v0l, v0h);
            unpack2(acc[oc][1][p], v1l, v1h);
            unpack2(acc[oc][2][p], v2l, v2h);
            unpack2(acc[oc][3][p], v3l, v3h);

            const int col = lane + p * 32;
            size_t base = ((size_t)(b * COUTD + cout0 + oc) * HDIM + h) * WDIM + col;

            {   // lo half: w = col
                float best = v0l; int idx = 0;
                if (v1l > best) { best = v1l; idx = 1; }
                if (v2l > best) { best = v2l; idx = 2; }
                if (v3l > best) { best = v3l; idx = 3; }
                float cv = (idx == 0) ? 1.0f : (idx == 1) ? -4.371139e-8f
                           : (idx == 2) ? -1.0f : 1.1924881e-8f;
                float sv = (idx == 0) ? 0.0f : (idx == 1) ? 1.0f
                           : (idx == 2) ? -8.742278e-8f : -1.0f;
                out[base]                = best;
                out[base + OUTPLANE]     = cv;
                out[base + 2 * OUTPLANE] = sv;
            }
            {   // hi half: w = col + 64
                float best = v0h; int idx = 0;
                if (v1h > best) { best = v1h; idx = 1; }
                if (v2h > best) { best = v2h; idx = 2; }
                if (v3h > best) { best = v3h; idx = 3; }
                float cv = (idx == 0) ? 1.0f : (idx == 1) ? -4.371139e-8f
                           : (idx == 2) ? -1.0f : 1.1924881e-8f;
                float sv = (idx == 0) ? 0.0f : (idx == 1) ? 1.0f
                           : (idx == 2) ? -8.742278e-8f : -1.0f;
                out[base + 64]                = best;
                out[base + 64 + OUTPLANE]     = cv;
                out[base + 64 + 2 * OUTPLANE] = sv;
            }
        }
    }
}

extern "C" void kernel_launch(void* const* d_in, const int* in_sizes, int n_in,
                              void* d_out, int out_size) {
    const float* f  = (const float*)d_in[0];
    const float* r0 = (const float*)d_in[1];
    const float* r1 = (const float*)d_in[2];
    const float* w  = (const float*)d_in[3];
    const float* wr = (const float*)d_in[4];

    precompute_kernel<<<(CIN * 9 * COUTD + 255) / 256, 256>>>(w, wr);

    dim3 grid(HDIM, BDIM);
    orient_conv_kernel<<<grid, 256>>>(f, r0, r1, (float*)d_out);
}

// round 14
// speedup vs baseline: 1.5827x; 1.1309x over previous
#include <cuda_runtime.h>
#include <cstdint>

#define CIN   32
#define COUTD 32
#define HDIM  128
#define WDIM  128
#define BDIM  4
#define PLANE (HDIM * WDIM)
#define OUTPLANE (BDIM * COUTD * PLANE)   /* 2097152 */
#define CSLICE (9 * COUTD * 12)           /* floats per channel slice: 3456 */

typedef unsigned long long u64;

// Coefficient table: per (cin, tap, cout): 12 floats (duplicated pairs):
// {c0,c0, s0,s0, wa,wa, wb,wb, wc,wc, wd,wd}  -> 48B per entry
__device__ __align__(16) float g_coef[CIN * CSLICE];

// ---------------- packed f32x2 helpers ----------------
static __device__ __forceinline__ u64 mul2(u64 a, u64 b) {
    u64 d; asm("mul.rn.f32x2 %0, %1, %2;" : "=l"(d) : "l"(a), "l"(b)); return d;
}
static __device__ __forceinline__ u64 fma2(u64 a, u64 b, u64 c) {
    u64 d; asm("fma.rn.f32x2 %0, %1, %2, %3;" : "=l"(d) : "l"(a), "l"(b), "l"(c)); return d;
}
static __device__ __forceinline__ u64 sub2(u64 a, u64 b) {
    u64 d; asm("sub.rn.f32x2 %0, %1, %2;" : "=l"(d) : "l"(a), "l"(b)); return d;
}
static __device__ __forceinline__ void unpack2(u64 a, float& lo, float& hi) {
    asm("mov.b64 {%0, %1}, %2;" : "=f"(lo), "=f"(hi) : "l"(a));
}
static __device__ __forceinline__ u64 pack2(float lo, float hi) {
    u64 d; asm("mov.b64 %0, {%1, %2};" : "=l"(d) : "f"(lo), "f"(hi)); return d;
}
static __device__ __forceinline__ u64 relu2(u64 a) {
    float lo, hi; unpack2(a, lo, hi);
    return pack2(fmaxf(lo, 0.f), fmaxf(hi, 0.f));
}

// ---------------- coefficient precompute ----------------
// e = (c*9 + tap)*32 + o
__global__ void precompute_kernel(const float* __restrict__ w,
                                  const float* __restrict__ wr) {
    int e = blockIdx.x * blockDim.x + threadIdx.x;
    if (e >= CIN * 9 * COUTD) return;
    int o   = e & 31;
    int tap = (e >> 5) % 9;
    int c   = e / (9 * COUTD);
    int i = tap / 3, j = tap % 3;

    const float* wrb = wr + (size_t)(o * CIN + c) * 9;
    const float* wb_ = w  + (size_t)(o * CIN + c) * 9;

    float ang = wrb[i * 3 + j];
    float s0, c0;
    sincosf(ang, &s0, &c0);

    // orientation-k weight = w rotated k times; rot1: wk[i,j] = w[2-j, i]
    float wa = wb_[i * 3 + j];                 // k=0, pairs with relu(u)
    float wb = wb_[(2 - j) * 3 + i];           // k=1, pairs with relu(v)
    float wc = wb_[(2 - i) * 3 + (2 - j)];     // k=2, pairs with relu(-u)
    float wd = wb_[j * 3 + (2 - i)];           // k=3, pairs with relu(-v)

    float* dst = g_coef + (size_t)e * 12;
    dst[0] = c0; dst[1] = c0;
    dst[2] = s0; dst[3] = s0;
    dst[4] = wa; dst[5] = wa;
    dst[6] = wb; dst[7] = wb;
    dst[8] = wc; dst[9] = wc;
    dst[10] = wd; dst[11] = wd;
}

// ---------------- main kernel ----------------
// Block: one (b, h) full row. 256 threads = 8 warps; warp w handles couts
// [w*4, w*4+4). Each lane handles P=2 packed pixel-pairs:
//   pair0 = (lane,     lane+64),  pair1 = (lane+32, lane+96)
// 36-step (tap,oc) software pipeline (coefficients fetched 1 step ahead).
// Register-pressure cuts vs the 415us kernel: single operand buffer and
// hoisted per-thread prefetch gather descriptors (no div/mod or bounds
// logic inside the channel loop).
__global__ void __launch_bounds__(256, 2)
orient_conv_kernel(const float* __restrict__ f,
                   const float* __restrict__ r0,
                   const float* __restrict__ r1,
                   float* __restrict__ out) {
    __shared__ float2 sm[2][3 * 3 * 66];   // [buf][a*198 + r*66 + kk]

    const int tid   = threadIdx.x;
    const int lane  = tid & 31;
    const int warp  = tid >> 5;
    const int cout0 = warp * 4;
    const int h     = blockIdx.x;
    const int b     = blockIdx.y;

    const u64 SGN = 0x8000000080000000ull;

    // ---- hoisted prefetch gather descriptors (computed once) ----
    int da[3], do1[3], do2[3], dd[3];
#pragma unroll
    for (int q = 0; q < 3; ++q) {
        int idx = tid + q * 256;
        if (idx < 594) {
            int a   = idx / 198;
            int rem = idx - a * 198;
            int r   = rem / 66;
            int kk  = rem - r * 66;
            int row = h - 1 + r;
            int g   = kk - 1;                     // -1..64
            bool rowok = (unsigned)row < (unsigned)HDIM;
            da[q]  = a;
            dd[q]  = idx;                         // float2 index within buffer
            do1[q] = (rowok && g >= 0)        ? row * WDIM + g      : -1;
            do2[q] = (rowok && g + 64 < WDIM) ? row * WDIM + g + 64 : -1;
        } else {
            da[q] = 0; dd[q] = -1; do1[q] = -1; do2[q] = -1;
        }
    }

    u64 acc[4][4][2];                    // [oc][orient][pair]
#pragma unroll
    for (int oc = 0; oc < 4; ++oc)
#pragma unroll
        for (int t = 0; t < 4; ++t) { acc[oc][t][0] = 0ull; acc[oc][t][1] = 0ull; }

    auto prefetch = [&](int c, int buf) {
        const size_t chanoff = (size_t)(b * CIN + c) * PLANE;
        const float* b0 = f  + chanoff;
        const float* b1 = r0 + chanoff;
        const float* b2 = r1 + chanoff;
#pragma unroll
        for (int q = 0; q < 3; ++q) {
            if (dd[q] >= 0) {
                const float* p = (da[q] == 0) ? b0 : (da[q] == 1) ? b1 : b2;
                float x1 = (do1[q] >= 0) ? __ldg(p + do1[q]) : 0.f;
                float x2 = (do2[q] >= 0) ? __ldg(p + do2[q]) : 0.f;
                sm[buf][dd[q]] = make_float2(x1, x2);
            }
        }
    };

    prefetch(0, 0);
    __syncthreads();

#pragma unroll 1
    for (int c = 0; c < CIN; ++c) {
        if (c + 1 < CIN) prefetch(c + 1, (c + 1) & 1);
        const int buf = c & 1;
        const ulonglong2* __restrict__ ctc =
            reinterpret_cast<const ulonglong2*>(g_coef) +
            ((size_t)(c * 9) * COUTD + cout0) * 3;

        // single operand buffer: [pair]
        u64 F[2], R0v[2], R1v[2];

        auto load_ops = [&](int tap) {
            const int i = tap / 3, j = tap % 3;     // compile-time in unrolled loop
            const float2* base = &sm[buf][i * 66];
#pragma unroll
            for (int p = 0; p < 2; ++p) {
                const int ent = lane + p * 32 + j;
                F[p]   = *reinterpret_cast<const u64*>(base + 0 * 198 + ent);
                R0v[p] = *reinterpret_cast<const u64*>(base + 1 * 198 + ent);
                R1v[p] = *reinterpret_cast<const u64*>(base + 2 * 198 + ent);
            }
        };

        ulonglong2 L0 = __ldg(ctc + 0);
        ulonglong2 L1 = __ldg(ctc + 1);
        ulonglong2 L2 = __ldg(ctc + 2);

#pragma unroll
        for (int t = 0; t < 36; ++t) {
            const int tap = t >> 2;
            const int oc  = t & 3;

            // load this tap's operands at its first step
            if (oc == 0) load_ops(tap);

            // issue next step's coefficient loads
            ulonglong2 N0, N1, N2;
            if (t < 35) {
                const ulonglong2* np = ctc + (size_t)((t + 1) >> 2) * (COUTD * 3)
                                           + (size_t)((t + 1) & 3) * 3;
                N0 = __ldg(np + 0); N1 = __ldg(np + 1); N2 = __ldg(np + 2);
            }

            const u64 NS = L0.y ^ SGN;   // packed -s

            // math for (tap, oc) on both pairs
#pragma unroll
            for (int p = 0; p < 2; ++p) {
                u64 u = fma2(L0.x, R0v[p], mul2(L0.y, R1v[p])); // c*r0+s*r1
                u64 v = fma2(NS,   R0v[p], mul2(L0.x, R1v[p])); // c*r1-s*r0

                u64 PU  = relu2(u);
                u64 PV  = relu2(v);
                u64 Fu  = mul2(F[p], u);
                u64 Fv  = mul2(F[p], v);
                u64 FPU = mul2(F[p], PU);
                u64 FPV = mul2(F[p], PV);
                u64 FMU = sub2(FPU, Fu);   // F*relu(-u) = F*relu(u) - F*u
                u64 FMV = sub2(FPV, Fv);   // F*relu(-v) = F*relu(v) - F*v

                acc[oc][0][p] = fma2(L1.x, FPU, acc[oc][0][p]);
                acc[oc][1][p] = fma2(L1.y, FPV, acc[oc][1][p]);
                acc[oc][2][p] = fma2(L2.x, FMU, acc[oc][2][p]);
                acc[oc][3][p] = fma2(L2.y, FMV, acc[oc][3][p]);
            }

            if (t < 35) { L0 = N0; L1 = N1; L2 = N2; }
        }
        __syncthreads();
    }

    // Epilogue: first-max argmax over the 4 orientations; write out / cos / sin.
#pragma unroll
    for (int oc = 0; oc < 4; ++oc) {
#pragma unroll
        for (int p = 0; p < 2; ++p) {
            float v0l, v0h, v1l, v1h, v2l, v2h, v3l, v3h;
            unpack2(acc[oc][0][p], v0l, v0h);
            unpack2(acc[oc][1][p], v1l, v1h);
            unpack2(acc[oc][2][p], v2l, v2h);
            unpack2(acc[oc][3][p], v3l, v3h);

            const int col = lane + p * 32;
            size_t base = ((size_t)(b * COUTD + cout0 + oc) * HDIM + h) * WDIM + col;

            {   // lo half: w = col
                float best = v0l; int idx = 0;
                if (v1l > best) { best = v1l; idx = 1; }
                if (v2l > best) { best = v2l; idx = 2; }
                if (v3l > best) { best = v3l; idx = 3; }
                float cv = (idx == 0) ? 1.0f : (idx == 1) ? -4.371139e-8f
                           : (idx == 2) ? -1.0f : 1.1924881e-8f;
                float sv = (idx == 0) ? 0.0f : (idx == 1) ? 1.0f
                           : (idx == 2) ? -8.742278e-8f : -1.0f;
                out[base]                = best;
                out[base + OUTPLANE]     = cv;
                out[base + 2 * OUTPLANE] = sv;
            }
            {   // hi half: w = col + 64
                float best = v0h; int idx = 0;
                if (v1h > best) { best = v1h; idx = 1; }
                if (v2h > best) { best = v2h; idx = 2; }
                if (v3h > best) { best = v3h; idx = 3; }
                float cv = (idx == 0) ? 1.0f : (idx == 1) ? -4.371139e-8f
                           : (idx == 2) ? -1.0f : 1.1924881e-8f;
                float sv = (idx == 0) ? 0.0f : (idx == 1) ? 1.0f
                           : (idx == 2) ? -8.742278e-8f : -1.0f;
                out[base + 64]                = best;
                out[base + 64 + OUTPLANE]     = cv;
                out[base + 64 + 2 * OUTPLANE] = sv;
            }
        }
    }
}

extern "C" void kernel_launch(void* const* d_in, const int* in_sizes, int n_in,
                              void* d_out, int out_size) {
    const float* f  = (const float*)d_in[0];
    const float* r0 = (const float*)d_in[1];
    const float* r1 = (const float*)d_in[2];
    const float* w  = (const float*)d_in[3];
    const float* wr = (const float*)d_in[4];

    precompute_kernel<<<(CIN * 9 * COUTD + 255) / 256, 256>>>(w, wr);

    dim3 grid(HDIM, BDIM);
    orient_conv_kernel<<<grid, 256>>>(f, r0, r1, (float*)d_out);
}

// round 15
// speedup vs baseline: 1.6564x; 1.0466x over previous
#include <cuda_runtime.h>
#include <cstdint>

#define CIN   32
#define COUTD 32
#define HDIM  128
#define WDIM  128
#define BDIM  4
#define PLANE (HDIM * WDIM)
#define OUTPLANE (BDIM * COUTD * PLANE)   /* 2097152 */
#define CSLICE (9 * COUTD * 12)           /* floats per channel slice: 3456 */

typedef unsigned long long u64;

// Coefficient table: per (cin, tap, cout): 12 floats (duplicated pairs):
// {c0,c0, s0,s0, wa,wa, wb,wb, wc,wc, wd,wd}  -> 48B per entry
__device__ __align__(16) float g_coef[CIN * CSLICE];

// ---------------- packed f32x2 helpers ----------------
static __device__ __forceinline__ u64 mul2(u64 a, u64 b) {
    u64 d; asm("mul.rn.f32x2 %0, %1, %2;" : "=l"(d) : "l"(a), "l"(b)); return d;
}
static __device__ __forceinline__ u64 fma2(u64 a, u64 b, u64 c) {
    u64 d; asm("fma.rn.f32x2 %0, %1, %2, %3;" : "=l"(d) : "l"(a), "l"(b), "l"(c)); return d;
}
static __device__ __forceinline__ u64 sub2(u64 a, u64 b) {
    u64 d; asm("sub.rn.f32x2 %0, %1, %2;" : "=l"(d) : "l"(a), "l"(b)); return d;
}
static __device__ __forceinline__ void unpack2(u64 a, float& lo, float& hi) {
    asm("mov.b64 {%0, %1}, %2;" : "=f"(lo), "=f"(hi) : "l"(a));
}
static __device__ __forceinline__ u64 pack2(float lo, float hi) {
    u64 d; asm("mov.b64 %0, {%1, %2};" : "=l"(d) : "f"(lo), "f"(hi)); return d;
}
static __device__ __forceinline__ u64 relu2(u64 a) {
    float lo, hi; unpack2(a, lo, hi);
    return pack2(fmaxf(lo, 0.f), fmaxf(hi, 0.f));
}

// ---------------- coefficient precompute ----------------
// e = (c*9 + tap)*32 + o
__global__ void precompute_kernel(const float* __restrict__ w,
                                  const float* __restrict__ wr) {
    int e = blockIdx.x * blockDim.x + threadIdx.x;
    if (e >= CIN * 9 * COUTD) return;
    int o   = e & 31;
    int tap = (e >> 5) % 9;
    int c   = e / (9 * COUTD);
    int i = tap / 3, j = tap % 3;

    const float* wrb = wr + (size_t)(o * CIN + c) * 9;
    const float* wb_ = w  + (size_t)(o * CIN + c) * 9;

    float ang = wrb[i * 3 + j];
    float s0, c0;
    sincosf(ang, &s0, &c0);

    // orientation-k weight = w rotated k times; rot1: wk[i,j] = w[2-j, i]
    float wa = wb_[i * 3 + j];                 // k=0, pairs with relu(u)
    float wb = wb_[(2 - j) * 3 + i];           // k=1, pairs with relu(v)
    float wc = wb_[(2 - i) * 3 + (2 - j)];     // k=2, pairs with relu(-u)
    float wd = wb_[j * 3 + (2 - i)];           // k=3, pairs with relu(-v)

    float* dst = g_coef + (size_t)e * 12;
    dst[0] = c0; dst[1] = c0;
    dst[2] = s0; dst[3] = s0;
    dst[4] = wa; dst[5] = wa;
    dst[6] = wb; dst[7] = wb;
    dst[8] = wc; dst[9] = wc;
    dst[10] = wd; dst[11] = wd;
}

// ---------------- main kernel ----------------
// Block: one (b, h) full row. 256 threads = 8 warps; warp w handles couts
// [w*4, w*4+4). Each lane handles P=2 packed pixel-pairs:
//   pair0 = (lane,     lane+64),  pair1 = (lane+32, lane+96)
// 36-step (tap,oc) software pipeline. R0/R1 operands for tap k+1 are loaded
// during tap k's oc==3 step (>=1 step of LDS->use distance); F is loaded at
// oc==0 where its latency hides under the u/v chain. Prefetch gather
// descriptors hoisted out of the channel loop.
__global__ void __launch_bounds__(256, 2)
orient_conv_kernel(const float* __restrict__ f,
                   const float* __restrict__ r0,
                   const float* __restrict__ r1,
                   float* __restrict__ out) {
    __shared__ float2 sm[2][3 * 3 * 66];   // [buf][a*198 + r*66 + kk]

    const int tid   = threadIdx.x;
    const int lane  = tid & 31;
    const int warp  = tid >> 5;
    const int cout0 = warp * 4;
    const int h     = blockIdx.x;
    const int b     = blockIdx.y;

    const u64 SGN = 0x8000000080000000ull;

    // ---- hoisted prefetch gather descriptors (computed once) ----
    int da[3], do1[3], do2[3], dd[3];
#pragma unroll
    for (int q = 0; q < 3; ++q) {
        int idx = tid + q * 256;
        if (idx < 594) {
            int a   = idx / 198;
            int rem = idx - a * 198;
            int r   = rem / 66;
            int kk  = rem - r * 66;
            int row = h - 1 + r;
            int g   = kk - 1;                     // -1..64
            bool rowok = (unsigned)row < (unsigned)HDIM;
            da[q]  = a;
            dd[q]  = idx;
            do1[q] = (rowok && g >= 0)        ? row * WDIM + g      : -1;
            do2[q] = (rowok && g + 64 < WDIM) ? row * WDIM + g + 64 : -1;
        } else {
            da[q] = 0; dd[q] = -1; do1[q] = -1; do2[q] = -1;
        }
    }

    u64 acc[4][4][2];                    // [oc][orient][pair]
#pragma unroll
    for (int oc = 0; oc < 4; ++oc)
#pragma unroll
        for (int t = 0; t < 4; ++t) { acc[oc][t][0] = 0ull; acc[oc][t][1] = 0ull; }

    auto prefetch = [&](int c, int buf) {
        const size_t chanoff = (size_t)(b * CIN + c) * PLANE;
        const float* b0 = f  + chanoff;
        const float* b1 = r0 + chanoff;
        const float* b2 = r1 + chanoff;
#pragma unroll
        for (int q = 0; q < 3; ++q) {
            if (dd[q] >= 0) {
                const float* p = (da[q] == 0) ? b0 : (da[q] == 1) ? b1 : b2;
                float x1 = (do1[q] >= 0) ? __ldg(p + do1[q]) : 0.f;
                float x2 = (do2[q] >= 0) ? __ldg(p + do2[q]) : 0.f;
                sm[buf][dd[q]] = make_float2(x1, x2);
            }
        }
    };

    prefetch(0, 0);
    __syncthreads();

#pragma unroll 1
    for (int c = 0; c < CIN; ++c) {
        if (c + 1 < CIN) prefetch(c + 1, (c + 1) & 1);
        const int buf = c & 1;
        const ulonglong2* __restrict__ ctc =
            reinterpret_cast<const ulonglong2*>(g_coef) +
            ((size_t)(c * 9) * COUTD + cout0) * 3;

        u64 F[2], R0v[2], R1v[2];

        auto load_F = [&](int tap) {
            const int i = tap / 3, j = tap % 3;
            const float2* base = &sm[buf][i * 66];
#pragma unroll
            for (int p = 0; p < 2; ++p)
                F[p] = *reinterpret_cast<const u64*>(base + lane + p * 32 + j);
        };
        auto load_R = [&](int tap) {
            const int i = tap / 3, j = tap % 3;
            const float2* base = &sm[buf][i * 66];
#pragma unroll
            for (int p = 0; p < 2; ++p) {
                const int ent = lane + p * 32 + j;
                R0v[p] = *reinterpret_cast<const u64*>(base + 198 + ent);
                R1v[p] = *reinterpret_cast<const u64*>(base + 2 * 198 + ent);
            }
        };

        load_R(0);
        ulonglong2 L0 = __ldg(ctc + 0);
        ulonglong2 L1 = __ldg(ctc + 1);
        ulonglong2 L2 = __ldg(ctc + 2);

#pragma unroll
        for (int t = 0; t < 36; ++t) {
            const int tap = t >> 2;
            const int oc  = t & 3;

            if (oc == 0) load_F(tap);    // F latency hides under the u/v chain

            // issue next step's coefficient loads
            ulonglong2 N0, N1, N2;
            if (t < 35) {
                const ulonglong2* np = ctc + (size_t)((t + 1) >> 2) * (COUTD * 3)
                                           + (size_t)((t + 1) & 3) * 3;
                N0 = __ldg(np + 0); N1 = __ldg(np + 1); N2 = __ldg(np + 2);
            }

            // rename current R operands, then preload next tap's R during oc==3
            u64 R0c[2], R1c[2];
            R0c[0] = R0v[0]; R0c[1] = R0v[1];
            R1c[0] = R1v[0]; R1c[1] = R1v[1];
            if (oc == 3 && tap < 8) load_R(tap + 1);

            const u64 NS = L0.y ^ SGN;   // packed -s

#pragma unroll
            for (int p = 0; p < 2; ++p) {
                u64 u = fma2(L0.x, R0c[p], mul2(L0.y, R1c[p])); // c*r0+s*r1
                u64 v = fma2(NS,   R0c[p], mul2(L0.x, R1c[p])); // c*r1-s*r0

                u64 PU  = relu2(u);
                u64 PV  = relu2(v);
                u64 Fu  = mul2(F[p], u);
                u64 Fv  = mul2(F[p], v);
                u64 FPU = mul2(F[p], PU);
                u64 FPV = mul2(F[p], PV);
                u64 FMU = sub2(FPU, Fu);   // F*relu(-u) = F*relu(u) - F*u
                u64 FMV = sub2(FPV, Fv);   // F*relu(-v) = F*relu(v) - F*v

                acc[oc][0][p] = fma2(L1.x, FPU, acc[oc][0][p]);
                acc[oc][1][p] = fma2(L1.y, FPV, acc[oc][1][p]);
                acc[oc][2][p] = fma2(L2.x, FMU, acc[oc][2][p]);
                acc[oc][3][p] = fma2(L2.y, FMV, acc[oc][3][p]);
            }

            if (t < 35) { L0 = N0; L1 = N1; L2 = N2; }
        }
        __syncthreads();
    }

    // Epilogue: first-max argmax over the 4 orientations; write out / cos / sin.
#pragma unroll
    for (int oc = 0; oc < 4; ++oc) {
#pragma unroll
        for (int p = 0; p < 2; ++p) {
            float v0l, v0h, v1l, v1h, v2l, v2h, v3l, v3h;
            unpack2(acc[oc][0][p], v0l, v0h);
            unpack2(acc[oc][1][p], v1l, v1h);
            unpack2(acc[oc][2][p], v2l, v2h);
            unpack2(acc[oc][3][p], v3l, v3h);

            const int col = lane + p * 32;
            size_t base = ((size_t)(b * COUTD + cout0 + oc) * HDIM + h) * WDIM + col;

            {   // lo half: w = col
                float best = v0l; int idx = 0;
                if (v1l > best) { best = v1l; idx = 1; }
                if (v2l > best) { best = v2l; idx = 2; }
                if (v3l > best) { best = v3l; idx = 3; }
                float cv = (idx == 0) ? 1.0f : (idx == 1) ? -4.371139e-8f
                           : (idx == 2) ? -1.0f : 1.1924881e-8f;
                float sv = (idx == 0) ? 0.0f : (idx == 1) ? 1.0f
                           : (idx == 2) ? -8.742278e-8f : -1.0f;
                out[base]                = best;
                out[base + OUTPLANE]     = cv;
                out[base + 2 * OUTPLANE] = sv;
            }
            {   // hi half: w = col + 64
                float best = v0h; int idx = 0;
                if (v1h > best) { best = v1h; idx = 1; }
                if (v2h > best) { best = v2h; idx = 2; }
                if (v3h > best) { best = v3h; idx = 3; }
                float cv = (idx == 0) ? 1.0f : (idx == 1) ? -4.371139e-8f
                           : (idx == 2) ? -1.0f : 1.1924881e-8f;
                float sv = (idx == 0) ? 0.0f : (idx == 1) ? 1.0f
                           : (idx == 2) ? -8.742278e-8f : -1.0f;
                out[base + 64]                = best;
                out[base + 64 + OUTPLANE]     = cv;
                out[base + 64 + 2 * OUTPLANE] = sv;
            }
        }
    }
}

extern "C" void kernel_launch(void* const* d_in, const int* in_sizes, int n_in,
                              void* d_out, int out_size) {
    const float* f  = (const float*)d_in[0];
    const float* r0 = (const float*)d_in[1];
    const float* r1 = (const float*)d_in[2];
    const float* w  = (const float*)d_in[3];
    const float* wr = (const float*)d_in[4];

    precompute_kernel<<<(CIN * 9 * COUTD + 255) / 256, 256>>>(w, wr);

    dim3 grid(HDIM, BDIM);
    orient_conv_kernel<<<grid, 256>>>(f, r0, r1, (float*)d_out);
}